// round 10
// baseline (speedup 1.0000x reference)
#include <cuda_runtime.h>
#include <cstdint>

#define NODES 50000
#define NPAD  50048            // 391 * 128
#define NEDGE 600000
#define DIM   128
#define EPSV  1e-5f

#define SA 36                  // As row stride (floats), conflict-free for ldmatrix
#define SW 136                 // Ws row stride (floats), conflict-free for b-fragment LDS

// ---------------- scratch (static device globals; no allocations) ----------
__device__ float g_bufA[NPAD * DIM];   // rows >= NODES stay 0 (never written)
__device__ float g_bufB[NPAD * DIM];
__device__ int   g_cnt[NODES];         // zero at load; prep re-zeroes every launch
__device__ int   g_off[NODES + 1];
__device__ int   g_pos[NODES];
__device__ int   g_csr[NEDGE];
__device__ int   g_bsum[64];
__device__ float g_dinvA[NODES], g_coefA[NODES];   // fill = 2 (layers 1,2)
__device__ float g_dinvB[NODES], g_coefB[NODES];   // fill = 1 (layer 3)

// ---------------- CSR build -------------------------------------------------
// edge_index is int32 (JAX x64 disabled downcasts int64 -> int32)
__global__ void count_deg_kernel(const int* __restrict__ ei) {
    int i = blockIdx.x * blockDim.x + threadIdx.x;
    if (i < NEDGE) atomicAdd(&g_cnt[ei[NEDGE + i]], 1);
}

// 49 blocks x 1024: block-local exclusive scan -> g_off, block totals -> g_bsum
__global__ void scan1_kernel() {
    __shared__ int wsum[32];
    int tid = threadIdx.x, lane = tid & 31, wid = tid >> 5;
    int i = blockIdx.x * 1024 + tid;
    int v = (i < NODES) ? g_cnt[i] : 0;
    int x = v;
    #pragma unroll
    for (int m = 1; m < 32; m <<= 1) {
        int y = __shfl_up_sync(0xffffffffu, x, m);
        if (lane >= m) x += y;
    }
    if (lane == 31) wsum[wid] = x;
    __syncthreads();
    if (wid == 0) {
        int w = wsum[lane];
        #pragma unroll
        for (int m = 1; m < 32; m <<= 1) {
            int y = __shfl_up_sync(0xffffffffu, w, m);
            if (lane >= m) w += y;
        }
        wsum[lane] = w;
    }
    __syncthreads();
    int incl = x + (wid ? wsum[wid - 1] : 0);
    if (i < NODES) g_off[i] = incl - v;
    if (tid == 1023) g_bsum[blockIdx.x] = incl;
}

// 49 blocks x 1024: warp-parallel block-base reduction, then per-node prep
__global__ void prep_kernel() {
    __shared__ int sbase;
    int tid = threadIdx.x, lane = tid & 31;
    int b = blockIdx.x;
    if (tid < 32) {
        // parallel reduction over g_bsum[0..b) (b <= 48)
        int s = (lane < b) ? g_bsum[lane] : 0;
        if (lane + 32 < b) s += g_bsum[lane + 32];
        #pragma unroll
        for (int m = 16; m; m >>= 1) s += __shfl_xor_sync(0xffffffffu, s, m);
        if (lane == 0) {
            sbase = s;
            if (b == 0) g_off[NODES] = NEDGE;
        }
    }
    __syncthreads();
    int i = b * 1024 + tid;
    if (i < NODES) {
        int off = sbase + g_off[i];
        g_off[i] = off;
        g_pos[i] = off;
        int c = g_cnt[i];
        g_cnt[i] = 0;
        g_dinvA[i] = rsqrtf((float)(c + 3));
        g_coefA[i] = 3.0f / (float)(c + 3);
        g_dinvB[i] = rsqrtf((float)(c + 2));
        g_coefB[i] = 2.0f / (float)(c + 2);
    }
}

__global__ void fill_csr_kernel(const int* __restrict__ ei) {
    int i = blockIdx.x * blockDim.x + threadIdx.x;
    if (i < NEDGE) {
        int s = ei[i];
        int d = ei[NEDGE + i];
        g_csr[atomicAdd(&g_pos[d], 1)] = s;
    }
}

// ---------------- aggregation: TWO warps per node, 8-edge batches -----------
// Each warp handles 64 of the 128 features (lane -> one float2).
// out[i] = coef[i]*h[i] + dinv[i] * sum_{e: dst=i} dinv[src_e] * h[src_e]
// Per-output-element addition order identical to the one-warp version.
__global__ void agg_kernel(const float* __restrict__ h,
                           float* __restrict__ o,
                           int which)
{
    int gw   = (blockIdx.x * blockDim.x + threadIdx.x) >> 5;  // global warp
    int lane = threadIdx.x & 31;
    int w    = gw >> 1;            // node
    int half = gw & 1;             // which 64-feature half
    if (w >= NODES) return;
    const float* dinv = which ? g_dinvB : g_dinvA;
    const float* coef = which ? g_coefB : g_coefA;

    int e0 = g_off[w], e1 = g_off[w + 1];
    const float2* h2 = (const float2*)h;       // 64 float2 per row
    const int col = half * 32 + lane;          // this lane's float2 index
    float2 a = make_float2(0.f, 0.f);

    int e = e0;
    for (; e + 8 <= e1; e += 8) {
        int s0 = g_csr[e],     s1 = g_csr[e + 1];
        int s2 = g_csr[e + 2], s3 = g_csr[e + 3];
        int s4 = g_csr[e + 4], s5 = g_csr[e + 5];
        int s6 = g_csr[e + 6], s7 = g_csr[e + 7];
        float d0 = __ldg(&dinv[s0]), d1 = __ldg(&dinv[s1]);
        float d2 = __ldg(&dinv[s2]), d3 = __ldg(&dinv[s3]);
        float d4 = __ldg(&dinv[s4]), d5 = __ldg(&dinv[s5]);
        float d6 = __ldg(&dinv[s6]), d7 = __ldg(&dinv[s7]);
        float2 v0 = h2[s0 * 64 + col];
        float2 v1 = h2[s1 * 64 + col];
        float2 v2 = h2[s2 * 64 + col];
        float2 v3 = h2[s3 * 64 + col];
        float2 v4 = h2[s4 * 64 + col];
        float2 v5 = h2[s5 * 64 + col];
        float2 v6 = h2[s6 * 64 + col];
        float2 v7 = h2[s7 * 64 + col];
        a.x += d0 * v0.x; a.y += d0 * v0.y;
        a.x += d1 * v1.x; a.y += d1 * v1.y;
        a.x += d2 * v2.x; a.y += d2 * v2.y;
        a.x += d3 * v3.x; a.y += d3 * v3.y;
        a.x += d4 * v4.x; a.y += d4 * v4.y;
        a.x += d5 * v5.x; a.y += d5 * v5.y;
        a.x += d6 * v6.x; a.y += d6 * v6.y;
        a.x += d7 * v7.x; a.y += d7 * v7.y;
    }
    for (; e < e1; e++) {
        int   s  = g_csr[e];
        float ds = __ldg(&dinv[s]);
        float2 v = h2[s * 64 + col];
        a.x += ds * v.x; a.y += ds * v.y;
    }

    float di = dinv[w], cf = coef[w];
    float2 hv = h2[w * 64 + col];
    float2 r;
    r.x = cf * hv.x + di * a.x;
    r.y = cf * hv.y + di * a.y;
    ((float2*)o)[w * 64 + col] = r;
}

// ---------------- tf32 tensor-core GEMM + fused epilogue -------------------
__device__ __forceinline__ uint32_t f2tf(float x) {
    uint32_t r;
    asm("cvt.rna.tf32.f32 %0, %1;" : "=r"(r) : "f"(x));
    return r;
}

__device__ __forceinline__ void mma_tf32(float* c, const uint32_t* a,
                                         uint32_t b0, uint32_t b1) {
    asm volatile("mma.sync.aligned.m16n8k8.row.col.f32.tf32.tf32.f32 "
                 "{%0,%1,%2,%3}, {%4,%5,%6,%7}, {%8,%9}, {%0,%1,%2,%3};"
                 : "+f"(c[0]), "+f"(c[1]), "+f"(c[2]), "+f"(c[3])
                 : "r"(a[0]), "r"(a[1]), "r"(a[2]), "r"(a[3]),
                   "r"(b0), "r"(b1));
}

// Block: 128 rows x 128 cols, 8 warps each owning 16 full rows.
// MODE 0: out = relu(LN(A@W + bias) * gamma + beta)
// MODE 1: out = A@W + bias + resid
template<int MODE>
__global__ __launch_bounds__(256)
void gemm_tc_kernel(const float* __restrict__ A, const float* __restrict__ W,
                    const float* __restrict__ bias,
                    const float* __restrict__ gamma, const float* __restrict__ beta,
                    const float* __restrict__ resid,
                    float* __restrict__ out)
{
    __shared__ float As[128 * SA];
    __shared__ float Ws[32 * SW];

    const int tid  = threadIdx.x;
    const int warp = tid >> 5, lane = tid & 31;
    const int row0 = blockIdx.x * 128;

    const uint32_t* wsb = (const uint32_t*)Ws;
    uint32_t as_u32 = (uint32_t)__cvta_generic_to_shared(As);

    float acc[16][4];
    #pragma unroll
    for (int j = 0; j < 16; j++)
        #pragma unroll
        for (int c = 0; c < 4; c++) acc[j][c] = 0.f;

    const int m  = lane >> 3, rr = lane & 7;
    const int ar = warp * 16 + (m & 1) * 8 + rr;
    const int ac = (m >> 1) * 4;

    for (int kb = 0; kb < 4; kb++) {
        // A chunk: 128 x 32 -> tf32 smem
        #pragma unroll
        for (int u = 0; u < 4; u++) {
            int idx = tid + 256 * u;
            int r = idx >> 3, c4 = (idx & 7) << 2;
            float4 t = *(const float4*)&A[(row0 + r) * DIM + kb * 32 + c4];
            uint4 v = make_uint4(f2tf(t.x), f2tf(t.y), f2tf(t.z), f2tf(t.w));
            *(uint4*)&As[r * SA + c4] = v;
        }
        // W chunk: 32 x 128 -> tf32 smem (k-major)
        #pragma unroll
        for (int u = 0; u < 4; u++) {
            int idx = tid + 256 * u;
            int k = idx >> 5, n4 = (idx & 31) << 2;
            float4 t = *(const float4*)&W[(kb * 32 + k) * DIM + n4];
            uint4 v = make_uint4(f2tf(t.x), f2tf(t.y), f2tf(t.z), f2tf(t.w));
            *(uint4*)&Ws[k * SW + n4] = v;
        }
        __syncthreads();

        #pragma unroll
        for (int ks = 0; ks < 4; ks++) {
            uint32_t a[4];
            uint32_t addr = as_u32 + (uint32_t)(ar * SA + ks * 8 + ac) * 4u;
            asm volatile("ldmatrix.sync.aligned.m8n8.x4.shared.b16 "
                         "{%0,%1,%2,%3}, [%4];"
                         : "=r"(a[0]), "=r"(a[1]), "=r"(a[2]), "=r"(a[3])
                         : "r"(addr));
            const int kk = ks * 8 + (lane & 3);
            const int nn = lane >> 2;
            #pragma unroll
            for (int j = 0; j < 16; j++) {
                uint32_t b0 = wsb[kk * SW + j * 8 + nn];
                uint32_t b1 = wsb[(kk + 4) * SW + j * 8 + nn];
                mma_tf32(acc[j], a, b0, b1);
            }
        }
        __syncthreads();
    }

    // epilogue: row held by 4 consecutive lanes -> shfl_xor 1,2 reduces it
    const int rA = row0 + warp * 16 + (lane >> 2);
    const int cb = 2 * (lane & 3);
    const float2* bias2  = (const float2*)bias;
    const float2* gam2   = (const float2*)gamma;
    const float2* bet2   = (const float2*)beta;
    const float2* resid2 = (const float2*)resid;
    float2* out2 = (float2*)out;

    #pragma unroll
    for (int half = 0; half < 2; half++) {
        int r = rA + half * 8;
        float v[32];
        #pragma unroll
        for (int j = 0; j < 16; j++) {
            float2 bv = __ldg(&bias2[j * 4 + (lane & 3)]);
            v[2 * j]     = acc[j][half * 2]     + bv.x;
            v[2 * j + 1] = acc[j][half * 2 + 1] + bv.y;
        }
        if (MODE == 0) {
            float s = 0.f;
            #pragma unroll
            for (int e = 0; e < 32; e++) s += v[e];
            s += __shfl_xor_sync(0xffffffffu, s, 1);
            s += __shfl_xor_sync(0xffffffffu, s, 2);
            float mu = s * (1.0f / 128.0f);
            float s2 = 0.f;
            #pragma unroll
            for (int e = 0; e < 32; e++) { float d = v[e] - mu; s2 += d * d; }
            s2 += __shfl_xor_sync(0xffffffffu, s2, 1);
            s2 += __shfl_xor_sync(0xffffffffu, s2, 2);
            float rs = rsqrtf(s2 * (1.0f / 128.0f) + EPSV);
            if (r < NODES) {
                #pragma unroll
                for (int j = 0; j < 16; j++) {
                    float2 gv = __ldg(&gam2[j * 4 + (lane & 3)]);
                    float2 be = __ldg(&bet2[j * 4 + (lane & 3)]);
                    float2 o;
                    o.x = fmaxf((v[2 * j]     - mu) * rs * gv.x + be.x, 0.f);
                    o.y = fmaxf((v[2 * j + 1] - mu) * rs * gv.y + be.y, 0.f);
                    out2[(r * DIM + j * 8 + cb) >> 1] = o;
                }
            }
        } else {
            if (r < NODES) {
                #pragma unroll
                for (int j = 0; j < 16; j++) {
                    float2 rv = __ldg(&resid2[(r * DIM + j * 8 + cb) >> 1]);
                    float2 o;
                    o.x = v[2 * j]     + rv.x;
                    o.y = v[2 * j + 1] + rv.y;
                    out2[(r * DIM + j * 8 + cb) >> 1] = o;
                }
            }
        }
    }
}

// ---------------- launch ----------------------------------------------------
extern "C" void kernel_launch(void* const* d_in, const int* in_sizes, int n_in,
                              void* d_out, int out_size)
{
    const float* x   = (const float*)d_in[0];
    const int*   ei  = (const int*)d_in[1];
    const float* W1 = (const float*)d_in[2];
    const float* b1 = (const float*)d_in[3];
    const float* g1 = (const float*)d_in[4];
    const float* be1= (const float*)d_in[5];
    const float* W2 = (const float*)d_in[6];
    const float* b2 = (const float*)d_in[7];
    const float* g2 = (const float*)d_in[8];
    const float* be2= (const float*)d_in[9];
    const float* W3 = (const float*)d_in[10];
    const float* b3 = (const float*)d_in[11];
    float* out = (float*)d_out;

    float* bufA = nullptr;
    float* bufB = nullptr;
    cudaGetSymbolAddress((void**)&bufA, g_bufA);
    cudaGetSymbolAddress((void**)&bufB, g_bufB);

    const int TB = 256;
    dim3 eb((NEDGE + TB - 1) / TB);

    // CSR build (4 launches)
    count_deg_kernel<<<eb, TB>>>(ei);
    scan1_kernel<<<49, 1024>>>();
    prep_kernel<<<49, 1024>>>();
    fill_csr_kernel<<<eb, TB>>>(ei);

    dim3 ab(NODES * 2 * 32 / TB);   // two warps per node -> 12500 blocks
    dim3 gb(NPAD / 128);            // 391 blocks

    // layer 1 (fill = 2)
    agg_kernel<<<ab, TB>>>(x, bufA, 0);
    gemm_tc_kernel<0><<<gb, TB>>>(bufA, W1, b1, g1, be1, nullptr, bufB);
    // layer 2 (fill = 2)
    agg_kernel<<<ab, TB>>>(bufB, bufA, 0);
    gemm_tc_kernel<0><<<gb, TB>>>(bufA, W2, b2, g2, be2, nullptr, bufB);
    // layer 3 (fill = 1) + residual
    agg_kernel<<<ab, TB>>>(bufB, bufA, 1);
    gemm_tc_kernel<1><<<gb, TB>>>(bufA, W3, b3, nullptr, nullptr, x, out);
}

// round 11
// speedup vs baseline: 1.1624x; 1.1624x over previous
#include <cuda_runtime.h>
#include <cstdint>

#define NODES 50000
#define NPAD  50048            // 391 * 128
#define NEDGE 600000
#define DIM   128
#define EPSV  1e-5f

#define SA 36                  // As row stride (floats), conflict-free for ldmatrix
#define SW 136                 // Ws row stride (floats), conflict-free for b-fragment LDS

// ---------------- scratch (static device globals; no allocations) ----------
__device__ float g_bufA[NPAD * DIM];   // agg outputs (rows >= NODES stay 0)
__device__ float g_bufB[NPAD * DIM];   // gemm1 output (scaled by dinvA)
__device__ float g_bufC[NPAD * DIM];   // x_scaled, later gemm2 output (scaled by dinvB)
__device__ int   g_cnt[NODES];         // zero at load; prep re-zeroes every launch
__device__ int   g_off[NODES + 1];
__device__ int   g_pos[NODES];
__device__ int   g_csr[NEDGE];
__device__ int   g_bsum[64];
__device__ float g_dinvA[NODES];       // rsqrt(deg+3)  (fill = 2, layers 1,2)
__device__ float g_dinvB[NODES];       // rsqrt(deg+2)  (fill = 1, layer 3)

// ---------------- CSR build -------------------------------------------------
// edge_index is int32 (JAX x64 disabled downcasts int64 -> int32)
__global__ void count_deg_kernel(const int* __restrict__ ei) {
    int i = blockIdx.x * blockDim.x + threadIdx.x;
    if (i < NEDGE) atomicAdd(&g_cnt[ei[NEDGE + i]], 1);
}

// 49 blocks x 1024: block-local exclusive scan -> g_off, block totals -> g_bsum
__global__ void scan1_kernel() {
    __shared__ int wsum[32];
    int tid = threadIdx.x, lane = tid & 31, wid = tid >> 5;
    int i = blockIdx.x * 1024 + tid;
    int v = (i < NODES) ? g_cnt[i] : 0;
    int x = v;
    #pragma unroll
    for (int m = 1; m < 32; m <<= 1) {
        int y = __shfl_up_sync(0xffffffffu, x, m);
        if (lane >= m) x += y;
    }
    if (lane == 31) wsum[wid] = x;
    __syncthreads();
    if (wid == 0) {
        int w = wsum[lane];
        #pragma unroll
        for (int m = 1; m < 32; m <<= 1) {
            int y = __shfl_up_sync(0xffffffffu, w, m);
            if (lane >= m) w += y;
        }
        wsum[lane] = w;
    }
    __syncthreads();
    int incl = x + (wid ? wsum[wid - 1] : 0);
    if (i < NODES) g_off[i] = incl - v;
    if (tid == 1023) g_bsum[blockIdx.x] = incl;
}

// 49 blocks x 1024: warp-parallel block-base reduction, then per-node prep
__global__ void prep_kernel() {
    __shared__ int sbase;
    int tid = threadIdx.x, lane = tid & 31;
    int b = blockIdx.x;
    if (tid < 32) {
        int s = (lane < b) ? g_bsum[lane] : 0;
        if (lane + 32 < b) s += g_bsum[lane + 32];
        #pragma unroll
        for (int m = 16; m; m >>= 1) s += __shfl_xor_sync(0xffffffffu, s, m);
        if (lane == 0) {
            sbase = s;
            if (b == 0) g_off[NODES] = NEDGE;
        }
    }
    __syncthreads();
    int i = b * 1024 + tid;
    if (i < NODES) {
        int off = sbase + g_off[i];
        g_off[i] = off;
        g_pos[i] = off;
        int c = g_cnt[i];
        g_cnt[i] = 0;
        g_dinvA[i] = rsqrtf((float)(c + 3));
        g_dinvB[i] = rsqrtf((float)(c + 2));
    }
}

__global__ void fill_csr_kernel(const int* __restrict__ ei) {
    int i = blockIdx.x * blockDim.x + threadIdx.x;
    if (i < NEDGE) {
        int s = ei[i];
        int d = ei[NEDGE + i];
        g_csr[atomicAdd(&g_pos[d], 1)] = s;
    }
}

// ---------------- x -> dinvA-scaled copy ------------------------------------
__global__ void scale_x_kernel(const float* __restrict__ x, float* __restrict__ xs) {
    int i = blockIdx.x * blockDim.x + threadIdx.x;   // float4 index
    if (i < NODES * 32) {
        int row = i >> 5;
        float d = g_dinvA[row];
        float4 v = *(const float4*)&x[i * 4];
        v.x *= d; v.y *= d; v.z *= d; v.w *= d;
        *(float4*)&xs[i * 4] = v;
    }
}

// ---------------- aggregation: one warp/node, prescaled rows, 8-edge batch --
// input hs already scaled by dinv_layer per row:
// out[i] = dinv[i] * ( sum_{e: dst=i} hs[src_e] + k * hs[i] ),  k = 1 + fill
__global__ void agg_kernel(const float* __restrict__ hs,
                           float* __restrict__ o,
                           int which, float k)   // which: 0 -> dinvA, 1 -> dinvB
{
    int w    = (blockIdx.x * blockDim.x + threadIdx.x) >> 5;
    int lane = threadIdx.x & 31;
    if (w >= NODES) return;
    const float* dinv = which ? g_dinvB : g_dinvA;

    int e0 = g_off[w], e1 = g_off[w + 1];
    const float4* h4 = (const float4*)hs;
    float4 a = make_float4(0.f, 0.f, 0.f, 0.f);

    int e = e0;
    for (; e + 8 <= e1; e += 8) {
        int s0 = g_csr[e],     s1 = g_csr[e + 1];
        int s2 = g_csr[e + 2], s3 = g_csr[e + 3];
        int s4 = g_csr[e + 4], s5 = g_csr[e + 5];
        int s6 = g_csr[e + 6], s7 = g_csr[e + 7];
        float4 v0 = h4[s0 * 32 + lane];
        float4 v1 = h4[s1 * 32 + lane];
        float4 v2 = h4[s2 * 32 + lane];
        float4 v3 = h4[s3 * 32 + lane];
        float4 v4 = h4[s4 * 32 + lane];
        float4 v5 = h4[s5 * 32 + lane];
        float4 v6 = h4[s6 * 32 + lane];
        float4 v7 = h4[s7 * 32 + lane];
        a.x += v0.x; a.y += v0.y; a.z += v0.z; a.w += v0.w;
        a.x += v1.x; a.y += v1.y; a.z += v1.z; a.w += v1.w;
        a.x += v2.x; a.y += v2.y; a.z += v2.z; a.w += v2.w;
        a.x += v3.x; a.y += v3.y; a.z += v3.z; a.w += v3.w;
        a.x += v4.x; a.y += v4.y; a.z += v4.z; a.w += v4.w;
        a.x += v5.x; a.y += v5.y; a.z += v5.z; a.w += v5.w;
        a.x += v6.x; a.y += v6.y; a.z += v6.z; a.w += v6.w;
        a.x += v7.x; a.y += v7.y; a.z += v7.z; a.w += v7.w;
    }
    for (; e < e1; e++) {
        int s = g_csr[e];
        float4 v = h4[s * 32 + lane];
        a.x += v.x; a.y += v.y; a.z += v.z; a.w += v.w;
    }

    float di = dinv[w];
    float4 hv = h4[w * 32 + lane];
    float4 r;
    r.x = di * (a.x + k * hv.x);
    r.y = di * (a.y + k * hv.y);
    r.z = di * (a.z + k * hv.z);
    r.w = di * (a.w + k * hv.w);
    ((float4*)o)[w * 32 + lane] = r;
}

// ---------------- tf32 tensor-core GEMM + fused epilogue -------------------
__device__ __forceinline__ uint32_t f2tf(float x) {
    uint32_t r;
    asm("cvt.rna.tf32.f32 %0, %1;" : "=r"(r) : "f"(x));
    return r;
}

__device__ __forceinline__ void mma_tf32(float* c, const uint32_t* a,
                                         uint32_t b0, uint32_t b1) {
    asm volatile("mma.sync.aligned.m16n8k8.row.col.f32.tf32.tf32.f32 "
                 "{%0,%1,%2,%3}, {%4,%5,%6,%7}, {%8,%9}, {%0,%1,%2,%3};"
                 : "+f"(c[0]), "+f"(c[1]), "+f"(c[2]), "+f"(c[3])
                 : "r"(a[0]), "r"(a[1]), "r"(a[2]), "r"(a[3]),
                   "r"(b0), "r"(b1));
}

// Block: 128 rows x 128 cols, 8 warps each owning 16 full rows.
// MODE 0: out = scl[r] * relu(LN(A@W + bias) * gamma + beta)   (scl = next layer's dinv)
// MODE 1: out = A@W + bias + resid
template<int MODE>
__global__ __launch_bounds__(256)
void gemm_tc_kernel(const float* __restrict__ A, const float* __restrict__ W,
                    const float* __restrict__ bias,
                    const float* __restrict__ gamma, const float* __restrict__ beta,
                    const float* __restrict__ resid, const float* __restrict__ scl,
                    float* __restrict__ out)
{
    __shared__ float As[128 * SA];
    __shared__ float Ws[32 * SW];

    const int tid  = threadIdx.x;
    const int warp = tid >> 5, lane = tid & 31;
    const int row0 = blockIdx.x * 128;

    const uint32_t* wsb = (const uint32_t*)Ws;
    uint32_t as_u32 = (uint32_t)__cvta_generic_to_shared(As);

    float acc[16][4];
    #pragma unroll
    for (int j = 0; j < 16; j++)
        #pragma unroll
        for (int c = 0; c < 4; c++) acc[j][c] = 0.f;

    const int m  = lane >> 3, rr = lane & 7;
    const int ar = warp * 16 + (m & 1) * 8 + rr;
    const int ac = (m >> 1) * 4;

    for (int kb = 0; kb < 4; kb++) {
        // A chunk: 128 x 32 -> tf32 smem
        #pragma unroll
        for (int u = 0; u < 4; u++) {
            int idx = tid + 256 * u;
            int r = idx >> 3, c4 = (idx & 7) << 2;
            float4 t = *(const float4*)&A[(row0 + r) * DIM + kb * 32 + c4];
            uint4 v = make_uint4(f2tf(t.x), f2tf(t.y), f2tf(t.z), f2tf(t.w));
            *(uint4*)&As[r * SA + c4] = v;
        }
        // W chunk: 32 x 128 -> tf32 smem (k-major)
        #pragma unroll
        for (int u = 0; u < 4; u++) {
            int idx = tid + 256 * u;
            int k = idx >> 5, n4 = (idx & 31) << 2;
            float4 t = *(const float4*)&W[(kb * 32 + k) * DIM + n4];
            uint4 v = make_uint4(f2tf(t.x), f2tf(t.y), f2tf(t.z), f2tf(t.w));
            *(uint4*)&Ws[k * SW + n4] = v;
        }
        __syncthreads();

        #pragma unroll
        for (int ks = 0; ks < 4; ks++) {
            uint32_t a[4];
            uint32_t addr = as_u32 + (uint32_t)(ar * SA + ks * 8 + ac) * 4u;
            asm volatile("ldmatrix.sync.aligned.m8n8.x4.shared.b16 "
                         "{%0,%1,%2,%3}, [%4];"
                         : "=r"(a[0]), "=r"(a[1]), "=r"(a[2]), "=r"(a[3])
                         : "r"(addr));
            const int kk = ks * 8 + (lane & 3);
            const int nn = lane >> 2;
            #pragma unroll
            for (int j = 0; j < 16; j++) {
                uint32_t b0 = wsb[kk * SW + j * 8 + nn];
                uint32_t b1 = wsb[(kk + 4) * SW + j * 8 + nn];
                mma_tf32(acc[j], a, b0, b1);
            }
        }
        __syncthreads();
    }

    // epilogue: row held by 4 consecutive lanes -> shfl_xor 1,2 reduces it
    const int rA = row0 + warp * 16 + (lane >> 2);
    const int cb = 2 * (lane & 3);
    const float2* bias2  = (const float2*)bias;
    const float2* gam2   = (const float2*)gamma;
    const float2* bet2   = (const float2*)beta;
    const float2* resid2 = (const float2*)resid;
    float2* out2 = (float2*)out;

    #pragma unroll
    for (int half = 0; half < 2; half++) {
        int r = rA + half * 8;
        float v[32];
        #pragma unroll
        for (int j = 0; j < 16; j++) {
            float2 bv = __ldg(&bias2[j * 4 + (lane & 3)]);
            v[2 * j]     = acc[j][half * 2]     + bv.x;
            v[2 * j + 1] = acc[j][half * 2 + 1] + bv.y;
        }
        if (MODE == 0) {
            float s = 0.f;
            #pragma unroll
            for (int e = 0; e < 32; e++) s += v[e];
            s += __shfl_xor_sync(0xffffffffu, s, 1);
            s += __shfl_xor_sync(0xffffffffu, s, 2);
            float mu = s * (1.0f / 128.0f);
            float s2 = 0.f;
            #pragma unroll
            for (int e = 0; e < 32; e++) { float d = v[e] - mu; s2 += d * d; }
            s2 += __shfl_xor_sync(0xffffffffu, s2, 1);
            s2 += __shfl_xor_sync(0xffffffffu, s2, 2);
            float rs = rsqrtf(s2 * (1.0f / 128.0f) + EPSV);
            if (r < NODES) {
                float sc = __ldg(&scl[r]);
                #pragma unroll
                for (int j = 0; j < 16; j++) {
                    float2 gv = __ldg(&gam2[j * 4 + (lane & 3)]);
                    float2 be = __ldg(&bet2[j * 4 + (lane & 3)]);
                    float2 o;
                    o.x = sc * fmaxf((v[2 * j]     - mu) * rs * gv.x + be.x, 0.f);
                    o.y = sc * fmaxf((v[2 * j + 1] - mu) * rs * gv.y + be.y, 0.f);
                    out2[(r * DIM + j * 8 + cb) >> 1] = o;
                }
            }
        } else {
            if (r < NODES) {
                #pragma unroll
                for (int j = 0; j < 16; j++) {
                    float2 rv = __ldg(&resid2[(r * DIM + j * 8 + cb) >> 1]);
                    float2 o;
                    o.x = v[2 * j]     + rv.x;
                    o.y = v[2 * j + 1] + rv.y;
                    out2[(r * DIM + j * 8 + cb) >> 1] = o;
                }
            }
        }
    }
}

// ---------------- launch ----------------------------------------------------
extern "C" void kernel_launch(void* const* d_in, const int* in_sizes, int n_in,
                              void* d_out, int out_size)
{
    const float* x   = (const float*)d_in[0];
    const int*   ei  = (const int*)d_in[1];
    const float* W1 = (const float*)d_in[2];
    const float* b1 = (const float*)d_in[3];
    const float* g1 = (const float*)d_in[4];
    const float* be1= (const float*)d_in[5];
    const float* W2 = (const float*)d_in[6];
    const float* b2 = (const float*)d_in[7];
    const float* g2 = (const float*)d_in[8];
    const float* be2= (const float*)d_in[9];
    const float* W3 = (const float*)d_in[10];
    const float* b3 = (const float*)d_in[11];
    float* out = (float*)d_out;

    float* bufA = nullptr;
    float* bufB = nullptr;
    float* bufC = nullptr;
    float* dinvA = nullptr;
    float* dinvB = nullptr;
    cudaGetSymbolAddress((void**)&bufA, g_bufA);
    cudaGetSymbolAddress((void**)&bufB, g_bufB);
    cudaGetSymbolAddress((void**)&bufC, g_bufC);
    cudaGetSymbolAddress((void**)&dinvA, g_dinvA);
    cudaGetSymbolAddress((void**)&dinvB, g_dinvB);

    const int TB = 256;
    dim3 eb((NEDGE + TB - 1) / TB);
    dim3 sb((NODES * 32 + TB - 1) / TB);

    // CSR build + x prescale (5 launches)
    count_deg_kernel<<<eb, TB>>>(ei);
    scan1_kernel<<<49, 1024>>>();
    prep_kernel<<<49, 1024>>>();
    fill_csr_kernel<<<eb, TB>>>(ei);
    scale_x_kernel<<<sb, TB>>>(x, bufC);          // bufC = dinvA .* x

    dim3 ab(NODES * 32 / TB);   // one warp per node
    dim3 gb(NPAD / 128);        // 391 blocks

    // layer 1 (fill = 2): gather prescaled x, output scaled by dinvA for layer 2
    agg_kernel<<<ab, TB>>>(bufC, bufA, 0, 3.0f);
    gemm_tc_kernel<0><<<gb, TB>>>(bufA, W1, b1, g1, be1, nullptr, dinvA, bufB);
    // layer 2 (fill = 2): output scaled by dinvB for layer 3
    agg_kernel<<<ab, TB>>>(bufB, bufA, 0, 3.0f);
    gemm_tc_kernel<0><<<gb, TB>>>(bufA, W2, b2, g2, be2, nullptr, dinvB, bufC);
    // layer 3 (fill = 1) + residual
    agg_kernel<<<ab, TB>>>(bufC, bufA, 1, 2.0f);
    gemm_tc_kernel<1><<<gb, TB>>>(bufA, W3, b3, nullptr, nullptr, x, nullptr, out);
}